// round 8
// baseline (speedup 1.0000x reference)
#include <cuda_runtime.h>
#include <cstdint>
#include <math.h>

// Problem constants
#define T_STEPS 512
#define BATCH   64
#define NHID    2048
#define NINP    64
#define NOUT    64

// Kernel config
#define NB 128                    // persistent CTAs (<=148 SMs, 1 CTA/SM)
#define NT 256                    // 8 warps = 2 per SMSP (latency hiding)
#define HT 16                     // h columns per CTA (NB*HT == NHID)
#define KC 128                    // k chunk (double buffered)
#define NCHUNK (NHID / KC)        // 16
#define GRPSZ  (NB / NCHUNK)      // 8 CTAs produce one chunk
#define CHUNK_FLOATS (KC * BATCH) // 8192 floats = 32 KB

// smem: sbuf(2 chunks) + Wh stripe + x_t + Wi stripe
#define SMEM_FLOATS (2 * CHUNK_FLOATS + HT * NHID + NINP * BATCH + HT * NINP)
#define SMEM_BYTES  (SMEM_FLOATS * 4)   // 217088

// State double buffer, TRANSPOSED: g_sT[buf][h*BATCH + b]
__device__ float    g_sT[2][NHID * BATCH];
// x transposed: g_xT[t][i*BATCH + b]
__device__ float    g_xT[T_STEPS * NINP * BATCH];
// per-chunk producer counters, padded to separate 128B lines
__device__ unsigned g_prod[NCHUNK * 32];
// readout partials
__device__ float    g_rpart[8][NOUT][BATCH];

// ---------------- prologue kernels ----------------
__global__ void reset_kernel() {
    if (threadIdx.x < NCHUNK) g_prod[threadIdx.x * 32] = 0u;
}

// Dummy no-op: shifts rnn_kernel to launch index 3 so ncu (which has been
// capturing launch index 3 in prior rounds) profiles the kernel that matters.
__global__ void dummy_kernel() {}

__global__ void transpose_x_kernel(const float* __restrict__ x) {
    __shared__ float xs[BATCH * (NINP + 1)];
    const int t = blockIdx.x;
    const float* xt = x + (size_t)t * (BATCH * NINP);
    for (int idx = threadIdx.x; idx < BATCH * NINP; idx += blockDim.x) {
        int b = idx >> 6, i = idx & 63;          // src [b][i], coalesced read
        xs[b * (NINP + 1) + i] = xt[idx];
    }
    __syncthreads();
    float* dst = g_xT + (size_t)t * (NINP * BATCH);
    for (int idx = threadIdx.x; idx < NINP * BATCH; idx += blockDim.x) {
        int i = idx >> 6, b = idx & 63;          // dst [i][b], coalesced write
        dst[idx] = xs[b * (NINP + 1) + i];       // padded -> conflict-free
    }
}

// ---------------- helpers ----------------
__device__ __forceinline__ void cpa16(float* s, const float* g) {
    unsigned sa = (unsigned)__cvta_generic_to_shared(s);
    asm volatile("cp.async.cg.shared.global [%0], [%1], 16;" :: "r"(sa), "l"(g) : "memory");
}
__device__ __forceinline__ void cpa_commit() { asm volatile("cp.async.commit_group;" ::: "memory"); }
__device__ __forceinline__ void cpa_wait1()  { asm volatile("cp.async.wait_group 1;" ::: "memory"); }
__device__ __forceinline__ void cpa_wait0()  { asm volatile("cp.async.wait_group 0;" ::: "memory"); }

__device__ __forceinline__ unsigned long long pk2(float v) {
    unsigned long long r;
    asm("mov.b64 %0, {%1, %1};" : "=l"(r) : "f"(v));
    return r;
}
__device__ __forceinline__ void fma2(unsigned long long& d, unsigned long long a, unsigned long long b) {
    asm("fma.rn.f32x2 %0, %1, %2, %0;" : "+l"(d) : "l"(a), "l"(b));
}
__device__ __forceinline__ float2 upk(unsigned long long v) {
    float2 r;
    asm("mov.b64 {%0, %1}, %2;" : "=f"(r.x), "=f"(r.y) : "l"(v));
    return r;
}

// Spin (thread 0) until chunk c's producers have all stored epoch `target`.
__device__ __forceinline__ void wait_flag(int c, unsigned target, int tid) {
    if (tid == 0) {
        unsigned v;
        do {
            asm volatile("ld.acquire.gpu.u32 %0, [%1];"
                         : "=r"(v) : "l"(&g_prod[c * 32]) : "memory");
        } while (v < target);
    }
    __syncthreads();   // also serves as post-compute barrier for previous chunk
}

// Release this CTA's step contribution.
__device__ __forceinline__ void signal_store(int grp, int tid) {
    __syncthreads();                 // all threads' state STGs issued
    if (tid == 0) {
        __threadfence();             // gpu-scope release of those stores
        atomicAdd(&g_prod[grp * 32], 1u);
    }
}

// ---------------- persistent recurrence kernel ----------------
__global__ void __launch_bounds__(NT, 1) rnn_kernel(
    const float* __restrict__ Wi,   // [NHID][NINP]
    const float* __restrict__ Wib,  // [NHID]
    const float* __restrict__ Wh,   // [NHID][NHID]
    const float* __restrict__ Ag,   // [NHID]
    const float* __restrict__ Om)   // [NHID]
{
    extern __shared__ float sm[];
    float* sbuf = sm;                        // 2 * 8192 floats (16B aligned)
    float* whs  = sm + 2 * CHUNK_FLOATS;     // HT*NHID, layout [k][hl]
    float* xbuf = whs + HT * NHID;           // NINP*BATCH, layout [i][b]
    float* wis  = xbuf + NINP * BATCH;       // NINP*HT,   layout [i][hl]

    const int tid = threadIdx.x;
    const int bq  = tid & 15;                // float4 index over b (b = bq*4..bq*4+3)
    const int hl  = tid >> 4;                // h index 0..15 (1 h per thread)
    const int h0g = blockIdx.x * HT;
    const int grp = blockIdx.x >> 3;         // chunk this CTA's h-slice belongs to

    // One-time loads: Wh stripe (k-major), Wi stripe (i-major), state init = 1
    for (int idx = tid; idx < HT * NHID; idx += NT) {
        int h = idx >> 11;                   // / NHID
        int k = idx & (NHID - 1);
        whs[k * HT + h] = Wh[(size_t)(h0g + h) * NHID + k];
    }
    for (int idx = tid; idx < HT * NINP; idx += NT) {
        int h = idx >> 6;
        int i = idx & 63;
        wis[i * HT + h] = Wi[(h0g + h) * NINP + i];
    }
    for (int idx = tid; idx < HT * BATCH; idx += NT) {
        g_sT[0][(h0g + (idx >> 6)) * BATCH + (idx & 63)] = 1.0f;
    }

    const float A0  = Ag[h0g + hl];
    const float o0  = Om[h0g + hl];
    const float bi0 = Wib[h0g + hl];

    float st[4];
    #pragma unroll
    for (int j = 0; j < 4; ++j) st[j] = 1.0f;

    signal_store(grp, tid);                  // initial state published (epoch 8)

    for (int t = 0; t < T_STEPS; ++t) {
        const int cur = t & 1, nxt = cur ^ 1;
        const float* S = g_sT[cur];
        const unsigned epoch = (unsigned)(GRPSZ * (t + 1));

        // stage x_t (4096 floats = 1024 vec4, 4 per thread)
        {
            const float* xsrc = g_xT + (size_t)t * (NINP * BATCH);
            #pragma unroll
            for (int j = 0; j < 4; ++j) { int v = tid + j * NT; cpa16(xbuf + v * 4, xsrc + v * 4); }
            cpa_commit();
        }
        // wait + prefetch first chunk (own group's chunk)
        wait_flag(grp, epoch, tid);
        {
            const float* src = S + grp * CHUNK_FLOATS;
            #pragma unroll
            for (int j = 0; j < 8; ++j) { int v = tid + j * NT; cpa16(sbuf + v * 4, src + v * 4); }
            cpa_commit();
        }

        unsigned long long m0 = pk2(0.f), m1 = pk2(0.f);
        int buf = 0;

        for (int i = 0; i < NCHUNK; ++i) {
            const int c = (grp + i) & (NCHUNK - 1);
            if (i + 1 < NCHUNK) {
                const int cn = (grp + i + 1) & (NCHUNK - 1);
                wait_flag(cn, epoch, tid);       // sync inside doubles as post-compute barrier
                const float* src = S + cn * CHUNK_FLOATS;
                float* dst = sbuf + (buf ^ 1) * CHUNK_FLOATS;
                #pragma unroll
                for (int j = 0; j < 8; ++j) { int v = tid + j * NT; cpa16(dst + v * 4, src + v * 4); }
                cpa_commit();
                cpa_wait1();                     // chunk c (and x, on i=0) has landed
            } else {
                cpa_wait0();                     // everything landed
            }
            __syncthreads();

            const ulonglong2* sb = (const ulonglong2*)(sbuf + buf * CHUNK_FLOATS);
            const float* wv = whs + c * KC * HT + hl;
            #pragma unroll 8
            for (int kk = 0; kk < KC; ++kk) {
                ulonglong2 sv = sb[kk * 16 + bq];          // LDS.128: state[k][b0..b3]
                float w = wv[kk * HT];                     // LDS.32 : Wh[h][k] (2-distinct/warp)
                unsigned long long w0 = pk2(w);
                fma2(m0, sv.x, w0); fma2(m1, sv.y, w0);
            }
            buf ^= 1;
        }

        // u_t = Wi x_t + b for this thread's (1h x 4b) tile
        float ua[4];
        #pragma unroll
        for (int j = 0; j < 4; ++j) ua[j] = bi0;
        const float4* xv = (const float4*)xbuf;
        #pragma unroll 8
        for (int i = 0; i < NINP; ++i) {
            float4 xs = xv[i * 16 + bq];
            float w = wis[i * HT + hl];
            ua[0] += xs.x * w; ua[1] += xs.y * w; ua[2] += xs.z * w; ua[3] += xs.w * w;
        }

        // epilogue: new = A*cos(omega*old + u) + matmul
        float2 p0 = upk(m0), p1 = upk(m1);
        float mm[4] = { p0.x, p0.y, p1.x, p1.y };
        float ns[4];
        #pragma unroll
        for (int j = 0; j < 4; ++j)
            ns[j] = A0 * cosf(o0 * st[j] + ua[j]) + mm[j];

        {
            float4 v = make_float4(ns[0], ns[1], ns[2], ns[3]);
            ((float4*)(g_sT[nxt] + (size_t)(h0g + hl) * BATCH))[bq] = v;   // coalesced STG.128
            #pragma unroll
            for (int j = 0; j < 4; ++j) st[j] = ns[j];
        }

        signal_store(grp, tid);
    }
}

// ---------------- readout, split: out[b][o] = sum_h sT[h][b]*Wr[o][h] + Wrb[o] ----------
__global__ void readout_part(const float* __restrict__ Wr)
{
    const int o  = blockIdx.x >> 3;
    const int sl = blockIdx.x & 7;
    const int b  = threadIdx.x;              // 64 threads
    const float* S  = g_sT[0];               // final state buffer (t=511 wrote buf 0)
    const float* wr = Wr + (size_t)o * NHID;
    float acc = 0.f;
    const int h0 = sl * (NHID / 8);
    #pragma unroll 4
    for (int h = h0; h < h0 + NHID / 8; ++h)
        acc += S[h * BATCH + b] * wr[h];
    g_rpart[sl][o][b] = acc;
}

__global__ void readout_comb(const float* __restrict__ Wrb, float* __restrict__ out)
{
    const int o = blockIdx.x;
    const int b = threadIdx.x;               // 64 threads
    float acc = Wrb[o];
    #pragma unroll
    for (int sl = 0; sl < 8; ++sl) acc += g_rpart[sl][o][b];
    out[b * NOUT + o] = acc;
}

// ---------------- launch ----------------
extern "C" void kernel_launch(void* const* d_in, const int* in_sizes, int n_in,
                              void* d_out, int out_size) {
    const float* x   = (const float*)d_in[0];
    const float* Wi  = (const float*)d_in[1];
    const float* Wib = (const float*)d_in[2];
    const float* Wh  = (const float*)d_in[3];
    const float* A   = (const float*)d_in[4];
    const float* Om  = (const float*)d_in[5];
    const float* Wr  = (const float*)d_in[6];
    const float* Wrb = (const float*)d_in[7];
    float* out = (float*)d_out;

    cudaFuncSetAttribute(rnn_kernel, cudaFuncAttributeMaxDynamicSharedMemorySize, SMEM_BYTES);

    reset_kernel<<<1, 32>>>();               // launch 0
    transpose_x_kernel<<<T_STEPS, 256>>>(x); // launch 1
    dummy_kernel<<<1, 32>>>();               // launch 2 (shifts rnn to index 3 for ncu)
    rnn_kernel<<<NB, NT, SMEM_BYTES>>>(Wi, Wib, Wh, A, Om);   // launch 3
    readout_part<<<NOUT * 8, BATCH>>>(Wr);   // launch 4
    readout_comb<<<NOUT, BATCH>>>(Wrb, out); // launch 5
}

// round 9
// speedup vs baseline: 2.1097x; 2.1097x over previous
#include <cuda_runtime.h>
#include <cstdint>
#include <math.h>

// Problem constants
#define T_STEPS 512
#define BATCH   64
#define NHID    2048
#define NINP    64
#define NOUT    64

// Kernel config
#define NB 128                    // persistent CTAs (1 CTA/SM, all co-resident)
#define NT 256                    // 8 warps = 2 per SMSP
#define HT 16                     // h columns per CTA (NB*HT == NHID)
#define KC 128                    // k chunk (double buffered)
#define NCHUNK (NHID / KC)        // 16
#define GRPSZ  (NB / NCHUNK)      // 8 CTAs produce one chunk
#define CHUNK_FLOATS (KC * BATCH) // 8192 floats = 32 KB

// smem: sbuf(2 chunks) + Wh stripe + x_t + Wi stripe
#define SMEM_FLOATS (2 * CHUNK_FLOATS + HT * NHID + NINP * BATCH + HT * NINP)
#define SMEM_BYTES  (SMEM_FLOATS * 4)   // 217088

// State double buffer, TRANSPOSED: g_sT[buf][h*BATCH + b]
__device__ float    g_sT[2][NHID * BATCH];
// x transposed: g_xT[t][i*BATCH + b]
__device__ float    g_xT[T_STEPS * NINP * BATCH];
// per-chunk producer counters, padded to separate 128B lines
__device__ unsigned g_prod[NCHUNK * 32];
// readout partials
__device__ float    g_rpart[8][NOUT][BATCH];

// ---------------- prologue kernels ----------------
__global__ void reset_kernel() {
    if (threadIdx.x < NCHUNK) g_prod[threadIdx.x * 32] = 0u;
}

// Dummy no-op: keeps rnn_kernel at launch index 3 (where ncu captures).
__global__ void dummy_kernel() {}

__global__ void transpose_x_kernel(const float* __restrict__ x) {
    __shared__ float xs[BATCH * (NINP + 1)];
    const int t = blockIdx.x;
    const float* xt = x + (size_t)t * (BATCH * NINP);
    for (int idx = threadIdx.x; idx < BATCH * NINP; idx += blockDim.x) {
        int b = idx >> 6, i = idx & 63;
        xs[b * (NINP + 1) + i] = xt[idx];
    }
    __syncthreads();
    float* dst = g_xT + (size_t)t * (NINP * BATCH);
    for (int idx = threadIdx.x; idx < NINP * BATCH; idx += blockDim.x) {
        int i = idx >> 6, b = idx & 63;
        dst[idx] = xs[b * (NINP + 1) + i];
    }
}

// ---------------- helpers ----------------
__device__ __forceinline__ void cpa16(float* s, const float* g) {
    unsigned sa = (unsigned)__cvta_generic_to_shared(s);
    asm volatile("cp.async.cg.shared.global [%0], [%1], 16;" :: "r"(sa), "l"(g) : "memory");
}
__device__ __forceinline__ void cpa_commit() { asm volatile("cp.async.commit_group;" ::: "memory"); }
__device__ __forceinline__ void cpa_wait1()  { asm volatile("cp.async.wait_group 1;" ::: "memory"); }
__device__ __forceinline__ void cpa_wait0()  { asm volatile("cp.async.wait_group 0;" ::: "memory"); }

__device__ __forceinline__ unsigned long long pk2(float v) {
    unsigned long long r;
    asm("mov.b64 %0, {%1, %1};" : "=l"(r) : "f"(v));
    return r;
}
__device__ __forceinline__ void fma2(unsigned long long& d, unsigned long long a, unsigned long long b) {
    asm("fma.rn.f32x2 %0, %1, %2, %0;" : "+l"(d) : "l"(a), "l"(b));
}

// Release this CTA's step contribution.
__device__ __forceinline__ void signal_store(int grp, int tid) {
    __syncthreads();                 // all threads' state STGs issued (block-visible)
    if (tid == 0) {
        __threadfence();             // gpu-scope release
        atomicAdd(&g_prod[grp * 32], 1u);
    }
}

// ---------------- persistent recurrence kernel ----------------
__global__ void __launch_bounds__(NT, 1) rnn_kernel(
    const float* __restrict__ Wi,   // [NHID][NINP]
    const float* __restrict__ Wib,  // [NHID]
    const float* __restrict__ Wh,   // [NHID][NHID]
    const float* __restrict__ Ag,   // [NHID]
    const float* __restrict__ Om)   // [NHID]
{
    extern __shared__ float sm[];
    float* sbuf = sm;                        // 2 * 8192 floats
    float* whs  = sm + 2 * CHUNK_FLOATS;     // HT*NHID, layout [k][h] (h contiguous)
    float* xbuf = whs + HT * NHID;           // NINP*BATCH, layout [i][b]
    float* wis  = xbuf + NINP * BATCH;       // NINP*HT,   layout [i][h]

    const int tid  = threadIdx.x;
    const int wrp  = tid >> 5;               // warp 0..7: owns k-rows [16w,16w+16) per chunk
    const int lane = tid & 31;
    const int hg   = lane >> 3;              // h group: h = hg*4 .. hg*4+3
    const int bg   = lane & 7;               // b group: b = bg*8 .. bg*8+7
    const int h0g  = blockIdx.x * HT;
    const int grp  = blockIdx.x >> 3;        // chunk this CTA's h-slice belongs to

    // epilogue ownership: thread -> 4 outputs (eh, eb..eb+3), bijective over 16h x 16 b-quads
    const int eh  = ((tid >> 6) << 2) | ((tid >> 1) & 3);
    const int ebq = (((tid >> 3) & 7) << 1) | (tid & 1);   // float4 index over b

    // One-time loads
    for (int idx = tid; idx < HT * NHID; idx += NT) {
        int h = idx >> 11;
        int k = idx & (NHID - 1);
        whs[k * HT + h] = Wh[(size_t)(h0g + h) * NHID + k];
    }
    for (int idx = tid; idx < HT * NINP; idx += NT) {
        int h = idx >> 6;
        int i = idx & 63;
        wis[i * HT + h] = Wi[(h0g + h) * NINP + i];
    }
    for (int idx = tid; idx < HT * BATCH; idx += NT) {
        g_sT[0][(h0g + (idx >> 6)) * BATCH + (idx & 63)] = 1.0f;
    }

    const float A0  = Ag[h0g + eh];
    const float o0  = Om[h0g + eh];
    const float bi0 = Wib[h0g + eh];

    float st[4] = {1.0f, 1.0f, 1.0f, 1.0f};

    signal_store(grp, tid);                  // initial state published

    for (int t = 0; t < T_STEPS; ++t) {
        const int cur = t & 1, nxt = cur ^ 1;
        const float* S = g_sT[cur];
        const unsigned epoch = (unsigned)(GRPSZ * (t + 1));

        // stage x_t
        {
            const float* xsrc = g_xT + (size_t)t * (NINP * BATCH);
            #pragma unroll
            for (int j = 0; j < 4; ++j) { int v = tid + j * NT; cpa16(xbuf + v * 4, xsrc + v * 4); }
            cpa_commit();
        }
        // parallel all-flags wait (threads 0..15 each poll one chunk counter)
        if (tid < NCHUNK) {
            unsigned v;
            do {
                asm volatile("ld.acquire.gpu.u32 %0, [%1];"
                             : "=r"(v) : "l"(&g_prod[tid * 32]) : "memory");
            } while (v < epoch);
        }
        __syncthreads();

        // prefetch first chunk
        {
            const int c0 = grp & (NCHUNK - 1);
            const float* src = S + c0 * CHUNK_FLOATS;
            #pragma unroll
            for (int j = 0; j < 8; ++j) { int v = tid + j * NT; cpa16(sbuf + v * 4, src + v * 4); }
            cpa_commit();
        }

        unsigned long long acc[4][4];
        #pragma unroll
        for (int h = 0; h < 4; ++h)
            #pragma unroll
            for (int p = 0; p < 4; ++p) acc[h][p] = 0ull;   // packed (0.f, 0.f)

        int buf = 0;
        for (int i = 0; i < NCHUNK; ++i) {
            const int c = (grp + i) & (NCHUNK - 1);
            if (i + 1 < NCHUNK) {
                const int cn = (grp + i + 1) & (NCHUNK - 1);
                const float* src = S + cn * CHUNK_FLOATS;
                float* dst = sbuf + (buf ^ 1) * CHUNK_FLOATS;
                #pragma unroll
                for (int j = 0; j < 8; ++j) { int v = tid + j * NT; cpa16(dst + v * 4, src + v * 4); }
                cpa_commit();
                cpa_wait1();                 // chunk c (and x on i=0) landed for this thread
            } else {
                cpa_wait0();
            }
            __syncthreads();                 // all threads' data landed

            // warp wrp computes k-rows [16*wrp, 16*wrp+16) of this chunk
            const float4* sv4 = (const float4*)(sbuf + buf * CHUNK_FLOATS) + (wrp * 16) * 16 + bg * 2;
            const float4* wv4 = (const float4*)whs + (c * KC + wrp * 16) * 4 + hg;
            #pragma unroll
            for (int kk = 0; kk < 16; ++kk) {
                ulonglong2 sa = *(const ulonglong2*)(sv4 + kk * 16);      // b0..b3 (2 pairs)
                ulonglong2 sb = *(const ulonglong2*)(sv4 + kk * 16 + 1);  // b4..b7
                float4 wq = wv4[kk * 4];                                  // 4 h weights
                unsigned long long w0 = pk2(wq.x), w1 = pk2(wq.y),
                                   w2 = pk2(wq.z), w3 = pk2(wq.w);
                fma2(acc[0][0], sa.x, w0); fma2(acc[0][1], sa.y, w0);
                fma2(acc[0][2], sb.x, w0); fma2(acc[0][3], sb.y, w0);
                fma2(acc[1][0], sa.x, w1); fma2(acc[1][1], sa.y, w1);
                fma2(acc[1][2], sb.x, w1); fma2(acc[1][3], sb.y, w1);
                fma2(acc[2][0], sa.x, w2); fma2(acc[2][1], sa.y, w2);
                fma2(acc[2][2], sb.x, w2); fma2(acc[2][3], sb.y, w2);
                fma2(acc[3][0], sa.x, w3); fma2(acc[3][1], sa.y, w3);
                fma2(acc[3][2], sb.x, w3); fma2(acc[3][3], sb.y, w3);
            }
            __syncthreads();                 // compute done before buf is refilled next iter
            buf ^= 1;
        }

        // cross-warp k-reduction through smem (overlay on sbuf; padded stride 36 floats)
        {
            float* myred = sm + wrp * (32 * 36) + lane * 36;
            #pragma unroll
            for (int h = 0; h < 4; ++h) {
                ((ulonglong2*)(myred + h * 8))[0] = make_ulonglong2(acc[h][0], acc[h][1]);
                ((ulonglong2*)(myred + h * 8))[1] = make_ulonglong2(acc[h][2], acc[h][3]);
            }
        }
        __syncthreads();
        float r0 = 0.f, r1 = 0.f, r2 = 0.f, r3 = 0.f;
        {
            const float* base = sm + (tid >> 3) * 36 + ((tid * 4) & 31);
            #pragma unroll
            for (int w2 = 0; w2 < 8; ++w2) {
                float4 v = *(const float4*)(base + w2 * (32 * 36));
                r0 += v.x; r1 += v.y; r2 += v.z; r3 += v.w;
            }
        }

        // u_t = Wi x_t + b for this thread's (eh, 4b) outputs
        float ua0 = bi0, ua1 = bi0, ua2 = bi0, ua3 = bi0;
        const float4* xv = (const float4*)xbuf;
        #pragma unroll 8
        for (int i2 = 0; i2 < NINP; ++i2) {
            float4 xs = xv[i2 * 16 + ebq];
            float wI = wis[i2 * HT + eh];
            ua0 += xs.x * wI; ua1 += xs.y * wI; ua2 += xs.z * wI; ua3 += xs.w * wI;
        }

        // epilogue
        float n0 = A0 * cosf(o0 * st[0] + ua0) + r0;
        float n1 = A0 * cosf(o0 * st[1] + ua1) + r1;
        float n2 = A0 * cosf(o0 * st[2] + ua2) + r2;
        float n3 = A0 * cosf(o0 * st[3] + ua3) + r3;
        float4 outv = make_float4(n0, n1, n2, n3);
        ((float4*)(g_sT[nxt] + (size_t)(h0g + eh) * BATCH))[ebq] = outv;
        st[0] = n0; st[1] = n1; st[2] = n2; st[3] = n3;

        signal_store(grp, tid);              // syncthreads inside also protects xbuf/redbuf
    }
}

// ---------------- readout, split: out[b][o] = sum_h sT[h][b]*Wr[o][h] + Wrb[o] ----------
__global__ void readout_part(const float* __restrict__ Wr)
{
    const int o  = blockIdx.x >> 3;
    const int sl = blockIdx.x & 7;
    const int b  = threadIdx.x;              // 64 threads
    const float* S  = g_sT[0];               // final state (t=511 wrote buf 0)
    const float* wr = Wr + (size_t)o * NHID;
    float acc = 0.f;
    const int h0 = sl * (NHID / 8);
    #pragma unroll 4
    for (int h = h0; h < h0 + NHID / 8; ++h)
        acc += S[h * BATCH + b] * wr[h];
    g_rpart[sl][o][b] = acc;
}

__global__ void readout_comb(const float* __restrict__ Wrb, float* __restrict__ out)
{
    const int o = blockIdx.x;
    const int b = threadIdx.x;               // 64 threads
    float acc = Wrb[o];
    #pragma unroll
    for (int sl = 0; sl < 8; ++sl) acc += g_rpart[sl][o][b];
    out[b * NOUT + o] = acc;
}

// ---------------- launch ----------------
extern "C" void kernel_launch(void* const* d_in, const int* in_sizes, int n_in,
                              void* d_out, int out_size) {
    const float* x   = (const float*)d_in[0];
    const float* Wi  = (const float*)d_in[1];
    const float* Wib = (const float*)d_in[2];
    const float* Wh  = (const float*)d_in[3];
    const float* A   = (const float*)d_in[4];
    const float* Om  = (const float*)d_in[5];
    const float* Wr  = (const float*)d_in[6];
    const float* Wrb = (const float*)d_in[7];
    float* out = (float*)d_out;

    cudaFuncSetAttribute(rnn_kernel, cudaFuncAttributeMaxDynamicSharedMemorySize, SMEM_BYTES);

    reset_kernel<<<1, 32>>>();               // launch 0
    transpose_x_kernel<<<T_STEPS, 256>>>(x); // launch 1
    dummy_kernel<<<1, 32>>>();               // launch 2
    rnn_kernel<<<NB, NT, SMEM_BYTES>>>(Wi, Wib, Wh, A, Om);   // launch 3 (ncu target)
    readout_part<<<NOUT * 8, BATCH>>>(Wr);   // launch 4
    readout_comb<<<NOUT, BATCH>>>(Wrb, out); // launch 5
}

// round 10
// speedup vs baseline: 2.8596x; 1.3554x over previous
#include <cuda_runtime.h>
#include <cstdint>
#include <math.h>

// Problem constants
#define T_STEPS 512
#define BATCH   64
#define NHID    2048
#define NINP    64
#define NOUT    64

// Kernel config
#define NB 128                    // persistent CTAs (1 CTA/SM, all co-resident)
#define NT 256                    // 8 warps = 2 per SMSP
#define HT 16                     // h columns per CTA (NB*HT == NHID)
#define KPW (NHID / 8)            // 256 k-rows per warp
#define NCHUNK 16                 // flag groups (bid>>3 produces one 16-h slice)
#define GRPSZ  (NB / NCHUNK)      // 8 CTAs per flag group

// smem: whs [k][16h] + xbuf [i][b] + wis [i][h] + red (8 warps x 32 lanes x 36)
#define WHS_FLOATS (HT * NHID)            // 32768
#define XBUF_FLOATS (NINP * BATCH)        // 4096
#define WIS_FLOATS (NINP * HT)            // 1024
#define RED_FLOATS (8 * 32 * 36)          // 9216
#define SMEM_FLOATS (WHS_FLOATS + XBUF_FLOATS + WIS_FLOATS + RED_FLOATS)
#define SMEM_BYTES  (SMEM_FLOATS * 4)     // 188416

// State double buffer, TRANSPOSED: g_sT[buf][k*BATCH + b]
__device__ float    g_sT[2][NHID * BATCH];
// x transposed: g_xT[t][i*BATCH + b]
__device__ float    g_xT[T_STEPS * NINP * BATCH];
// per-group producer counters, padded to separate 128B lines
__device__ unsigned g_prod[NCHUNK * 32];
// readout partials
__device__ float    g_rpart[8][NOUT][BATCH];

// ---------------- prologue kernels ----------------
__global__ void reset_kernel() {
    if (threadIdx.x < NCHUNK) g_prod[threadIdx.x * 32] = 0u;
}

// Dummy no-op: keeps rnn_kernel at launch index 3 (where ncu captures).
__global__ void dummy_kernel() {}

__global__ void transpose_x_kernel(const float* __restrict__ x) {
    __shared__ float xs[BATCH * (NINP + 1)];
    const int t = blockIdx.x;
    const float* xt = x + (size_t)t * (BATCH * NINP);
    for (int idx = threadIdx.x; idx < BATCH * NINP; idx += blockDim.x) {
        int b = idx >> 6, i = idx & 63;
        xs[b * (NINP + 1) + i] = xt[idx];
    }
    __syncthreads();
    float* dst = g_xT + (size_t)t * (NINP * BATCH);
    for (int idx = threadIdx.x; idx < NINP * BATCH; idx += blockDim.x) {
        int i = idx >> 6, b = idx & 63;
        dst[idx] = xs[b * (NINP + 1) + i];
    }
}

// ---------------- helpers ----------------
__device__ __forceinline__ void cpa16(float* s, const float* g) {
    unsigned sa = (unsigned)__cvta_generic_to_shared(s);
    asm volatile("cp.async.cg.shared.global [%0], [%1], 16;" :: "r"(sa), "l"(g) : "memory");
}
__device__ __forceinline__ void cpa_commit() { asm volatile("cp.async.commit_group;" ::: "memory"); }
__device__ __forceinline__ void cpa_wait0()  { asm volatile("cp.async.wait_group 0;" ::: "memory"); }

__device__ __forceinline__ unsigned long long pk2(float v) {
    unsigned long long r;
    asm("mov.b64 %0, {%1, %1};" : "=l"(r) : "f"(v));
    return r;
}
__device__ __forceinline__ void fma2(unsigned long long& d, unsigned long long a, unsigned long long b) {
    asm("fma.rn.f32x2 %0, %1, %2, %0;" : "+l"(d) : "l"(a), "l"(b));
}
// 16B L2-coherent load as a pre-packed f32x2 pair (bypasses L1 -> no staleness).
__device__ __forceinline__ void ldcg2(const float* p, unsigned long long& a, unsigned long long& b) {
    asm volatile("ld.global.cg.v2.u64 {%0, %1}, [%2];" : "=l"(a), "=l"(b) : "l"(p));
}

// Release this CTA's step contribution.
__device__ __forceinline__ void signal_store(int grp, int tid) {
    __syncthreads();                 // all threads' state STGs issued
    if (tid == 0) {
        __threadfence();             // gpu-scope release
        atomicAdd(&g_prod[grp * 32], 1u);
    }
}

// ---------------- persistent recurrence kernel ----------------
__global__ void __launch_bounds__(NT, 1) rnn_kernel(
    const float* __restrict__ Wi,   // [NHID][NINP]
    const float* __restrict__ Wib,  // [NHID]
    const float* __restrict__ Wh,   // [NHID][NHID]
    const float* __restrict__ Ag,   // [NHID]
    const float* __restrict__ Om)   // [NHID]
{
    extern __shared__ float sm[];
    float* whs  = sm;                        // [k][16h], h contiguous
    float* xbuf = whs + WHS_FLOATS;          // [i][b]
    float* wis  = xbuf + XBUF_FLOATS;        // [i][h]
    float* red  = wis + WIS_FLOATS;          // 8 x 32 x 36

    const int tid  = threadIdx.x;
    const int wrp  = tid >> 5;
    const int lane = tid & 31;
    const int hg   = lane >> 3;              // h group: h = hg*4 .. hg*4+3
    const int bg   = lane & 7;               // b quad within each 32-half
    const int h0g  = blockIdx.x * HT;
    const int grp  = blockIdx.x >> 3;

    // epilogue ownership (bijective over 16h x 16 b-quads):
    const int eh  = ((tid >> 6) << 2) | ((tid >> 1) & 3);
    const int ebq = ((tid & 1) << 3) | ((tid >> 3) & 7);   // float4 index over b

    // One-time loads
    for (int idx = tid; idx < HT * NHID; idx += NT) {
        int h = idx >> 11;
        int k = idx & (NHID - 1);
        whs[k * HT + h] = Wh[(size_t)(h0g + h) * NHID + k];
    }
    for (int idx = tid; idx < HT * NINP; idx += NT) {
        int h = idx >> 6;
        int i = idx & 63;
        wis[i * HT + h] = Wi[(h0g + h) * NINP + i];
    }
    for (int idx = tid; idx < HT * BATCH; idx += NT) {
        g_sT[0][(h0g + (idx >> 6)) * BATCH + (idx & 63)] = 1.0f;
    }

    const float A0  = Ag[h0g + eh];
    const float o0  = Om[h0g + eh];
    const float bi0 = Wib[h0g + eh];

    float st[4] = {1.0f, 1.0f, 1.0f, 1.0f};

    signal_store(grp, tid);                  // initial state published

    // rotated k range per CTA (spreads L2 line pressure); two contiguous segments
    const int kbase = (wrp * KPW + ((blockIdx.x & 127) << 4)) & (NHID - 1);
    int len1 = NHID - kbase; if (len1 > KPW) len1 = KPW;
    const int len2 = KPW - len1;

    for (int t = 0; t < T_STEPS; ++t) {
        const int cur = t & 1, nxt = cur ^ 1;
        const float* S = g_sT[cur];
        const unsigned epoch = (unsigned)(GRPSZ * (t + 1));

        // stage x_t (small; lands before u-loop)
        {
            const float* xsrc = g_xT + (size_t)t * (NINP * BATCH);
            #pragma unroll
            for (int j = 0; j < 4; ++j) { int v = tid + j * NT; cpa16(xbuf + v * 4, xsrc + v * 4); }
            cpa_commit();
        }
        // parallel all-flags wait (threads 0..15 poll one counter each)
        if (tid < NCHUNK) {
            unsigned v;
            do {
                asm volatile("ld.acquire.gpu.u32 %0, [%1];"
                             : "=r"(v) : "l"(&g_prod[tid * 32]) : "memory");
            } while (v < epoch);
        }
        __syncthreads();

        unsigned long long acc[4][4];
        #pragma unroll
        for (int h = 0; h < 4; ++h)
            #pragma unroll
            for (int p = 0; p < 4; ++p) acc[h][p] = 0ull;

        // main MAC loop: state from L2 (LDG.cg), weights from smem
        #pragma unroll
        for (int seg = 0; seg < 2; ++seg) {
            const int ks  = seg ? 0    : kbase;
            const int len = seg ? len2 : len1;
            const float*  sp = S + (size_t)ks * BATCH + bg * 4;
            const float4* wp = (const float4*)whs + ks * 4 + hg;
            #pragma unroll 8
            for (int ki = 0; ki < len; ++ki) {
                unsigned long long s0, s1, s2, s3;
                ldcg2(sp + ki * BATCH,      s0, s1);   // b: bg*4..bg*4+3
                ldcg2(sp + ki * BATCH + 32, s2, s3);   // b: 32+bg*4..+3
                float4 wq = wp[ki * 4];                // 4 h weights (broadcast LDS.128)
                unsigned long long w0 = pk2(wq.x), w1 = pk2(wq.y),
                                   w2 = pk2(wq.z), w3 = pk2(wq.w);
                fma2(acc[0][0], s0, w0); fma2(acc[0][1], s1, w0);
                fma2(acc[0][2], s2, w0); fma2(acc[0][3], s3, w0);
                fma2(acc[1][0], s0, w1); fma2(acc[1][1], s1, w1);
                fma2(acc[1][2], s2, w1); fma2(acc[1][3], s3, w1);
                fma2(acc[2][0], s0, w2); fma2(acc[2][1], s1, w2);
                fma2(acc[2][2], s2, w2); fma2(acc[2][3], s3, w2);
                fma2(acc[3][0], s0, w3); fma2(acc[3][1], s1, w3);
                fma2(acc[3][2], s2, w3); fma2(acc[3][3], s3, w3);
            }
        }

        // cross-warp k-reduction through smem (padded stride 36 floats)
        {
            float* myred = red + wrp * (32 * 36) + lane * 36;
            #pragma unroll
            for (int h = 0; h < 4; ++h) {
                ((ulonglong2*)(myred + h * 8))[0] = make_ulonglong2(acc[h][0], acc[h][1]);
                ((ulonglong2*)(myred + h * 8))[1] = make_ulonglong2(acc[h][2], acc[h][3]);
            }
        }
        cpa_wait0();                         // x landed (this thread's part)
        __syncthreads();                     // red + xbuf visible to all

        float r0 = 0.f, r1 = 0.f, r2 = 0.f, r3 = 0.f;
        {
            // reader (tid) gathers h' = (tid>>1)&3, half q = tid&1 from source lane
            // row (tid>>3): matches (eh, ebq) ownership above.
            const float* base = red + (tid >> 3) * 36 + ((tid * 4) & 31);
            #pragma unroll
            for (int w2 = 0; w2 < 8; ++w2) {
                float4 v = *(const float4*)(base + w2 * (32 * 36));
                r0 += v.x; r1 += v.y; r2 += v.z; r3 += v.w;
            }
        }

        // u_t = Wi x_t + b for this thread's (eh, 4b) outputs
        float ua0 = bi0, ua1 = bi0, ua2 = bi0, ua3 = bi0;
        const float4* xv = (const float4*)xbuf;
        #pragma unroll 8
        for (int i2 = 0; i2 < NINP; ++i2) {
            float4 xs = xv[i2 * 16 + ebq];
            float wI = wis[i2 * HT + eh];
            ua0 += xs.x * wI; ua1 += xs.y * wI; ua2 += xs.z * wI; ua3 += xs.w * wI;
        }

        // epilogue
        float n0 = A0 * cosf(o0 * st[0] + ua0) + r0;
        float n1 = A0 * cosf(o0 * st[1] + ua1) + r1;
        float n2 = A0 * cosf(o0 * st[2] + ua2) + r2;
        float n3 = A0 * cosf(o0 * st[3] + ua3) + r3;
        ((float4*)(g_sT[nxt] + (size_t)(h0g + eh) * BATCH))[ebq] = make_float4(n0, n1, n2, n3);
        st[0] = n0; st[1] = n1; st[2] = n2; st[3] = n3;

        signal_store(grp, tid);
    }
}

// ---------------- readout, split: out[b][o] = sum_h sT[h][b]*Wr[o][h] + Wrb[o] ----------
__global__ void readout_part(const float* __restrict__ Wr)
{
    const int o  = blockIdx.x >> 3;
    const int sl = blockIdx.x & 7;
    const int b  = threadIdx.x;              // 64 threads
    const float* S  = g_sT[0];               // final state (t=511 wrote buf 0)
    const float* wr = Wr + (size_t)o * NHID;
    float acc = 0.f;
    const int h0 = sl * (NHID / 8);
    #pragma unroll 4
    for (int h = h0; h < h0 + NHID / 8; ++h)
        acc += S[h * BATCH + b] * wr[h];
    g_rpart[sl][o][b] = acc;
}

__global__ void readout_comb(const float* __restrict__ Wrb, float* __restrict__ out)
{
    const int o = blockIdx.x;
    const int b = threadIdx.x;               // 64 threads
    float acc = Wrb[o];
    #pragma unroll
    for (int sl = 0; sl < 8; ++sl) acc += g_rpart[sl][o][b];
    out[b * NOUT + o] = acc;
}

// ---------------- launch ----------------
extern "C" void kernel_launch(void* const* d_in, const int* in_sizes, int n_in,
                              void* d_out, int out_size) {
    const float* x   = (const float*)d_in[0];
    const float* Wi  = (const float*)d_in[1];
    const float* Wib = (const float*)d_in[2];
    const float* Wh  = (const float*)d_in[3];
    const float* A   = (const float*)d_in[4];
    const float* Om  = (const float*)d_in[5];
    const float* Wr  = (const float*)d_in[6];
    const float* Wrb = (const float*)d_in[7];
    float* out = (float*)d_out;

    cudaFuncSetAttribute(rnn_kernel, cudaFuncAttributeMaxDynamicSharedMemorySize, SMEM_BYTES);

    reset_kernel<<<1, 32>>>();               // launch 0
    transpose_x_kernel<<<T_STEPS, 256>>>(x); // launch 1
    dummy_kernel<<<1, 32>>>();               // launch 2
    rnn_kernel<<<NB, NT, SMEM_BYTES>>>(Wi, Wib, Wh, A, Om);   // launch 3 (ncu target)
    readout_part<<<NOUT * 8, BATCH>>>(Wr);   // launch 4
    readout_comb<<<NOUT, BATCH>>>(Wrb, out); // launch 5
}

// round 11
// speedup vs baseline: 2.8691x; 1.0033x over previous
#include <cuda_runtime.h>
#include <cstdint>
#include <math.h>

// Problem constants
#define T_STEPS 512
#define BATCH   64
#define NHID    2048
#define NINP    64
#define NOUT    64

// Kernel config
#define NB 128                    // persistent CTAs (1 CTA/SM, all co-resident)
#define NT 256                    // 8 warps = 2 per SMSP
#define HT 16                     // h columns per CTA (NB*HT == NHID)
#define KPW (NHID / 8)            // 256 k-rows per warp
#define NCHUNK 16                 // flag groups (bid>>3 produces one 16-h slice)
#define GRPSZ  (NB / NCHUNK)      // 8 CTAs per flag group

// smem: whs [k][16h] + xbuf [i][b] + wis [i][h] + red (8 warps x 32 lanes x 36)
#define WHS_FLOATS (HT * NHID)            // 32768
#define XBUF_FLOATS (NINP * BATCH)        // 4096
#define WIS_FLOATS (NINP * HT)            // 1024
#define RED_FLOATS (8 * 32 * 36)          // 9216
#define SMEM_FLOATS (WHS_FLOATS + XBUF_FLOATS + WIS_FLOATS + RED_FLOATS)
#define SMEM_BYTES  (SMEM_FLOATS * 4)     // 188416

// State double buffer, TRANSPOSED: g_sT[buf][k*BATCH + b]
__device__ float    g_sT[2][NHID * BATCH];
// x transposed: g_xT[t][i*BATCH + b]
__device__ float    g_xT[T_STEPS * NINP * BATCH];
// per-group producer counters, padded to separate 128B lines
__device__ unsigned g_prod[NCHUNK * 32];
// readout partials
__device__ float    g_rpart[8][NOUT][BATCH];

// ---------------- prologue kernels ----------------
__global__ void reset_kernel() {
    if (threadIdx.x < NCHUNK) g_prod[threadIdx.x * 32] = 0u;
}

// Dummy no-op: keeps rnn_kernel at launch index 3 (where ncu captures).
__global__ void dummy_kernel() {}

__global__ void transpose_x_kernel(const float* __restrict__ x) {
    __shared__ float xs[BATCH * (NINP + 1)];
    const int t = blockIdx.x;
    const float* xt = x + (size_t)t * (BATCH * NINP);
    for (int idx = threadIdx.x; idx < BATCH * NINP; idx += blockDim.x) {
        int b = idx >> 6, i = idx & 63;
        xs[b * (NINP + 1) + i] = xt[idx];
    }
    __syncthreads();
    float* dst = g_xT + (size_t)t * (NINP * BATCH);
    for (int idx = threadIdx.x; idx < NINP * BATCH; idx += blockDim.x) {
        int i = idx >> 6, b = idx & 63;
        dst[idx] = xs[b * (NINP + 1) + i];
    }
}

// ---------------- helpers ----------------
__device__ __forceinline__ void cpa16(float* s, const float* g) {
    unsigned sa = (unsigned)__cvta_generic_to_shared(s);
    asm volatile("cp.async.cg.shared.global [%0], [%1], 16;" :: "r"(sa), "l"(g) : "memory");
}
__device__ __forceinline__ void cpa_commit() { asm volatile("cp.async.commit_group;" ::: "memory"); }
__device__ __forceinline__ void cpa_wait0()  { asm volatile("cp.async.wait_group 0;" ::: "memory"); }

__device__ __forceinline__ unsigned long long pk2(float v) {
    unsigned long long r;
    asm("mov.b64 %0, {%1, %1};" : "=l"(r) : "f"(v));
    return r;
}
__device__ __forceinline__ void fma2(unsigned long long& d, unsigned long long a, unsigned long long b) {
    asm("fma.rn.f32x2 %0, %1, %2, %0;" : "+l"(d) : "l"(a), "l"(b));
}
// 16B L2-coherent load as a pre-packed f32x2 pair (bypasses L1 -> no staleness).
__device__ __forceinline__ void ldcg2(const float* p, unsigned long long& a, unsigned long long& b) {
    asm volatile("ld.global.cg.v2.u64 {%0, %1}, [%2];" : "=l"(a), "=l"(b) : "l"(p));
}

// Release this CTA's step contribution.
__device__ __forceinline__ void signal_store(int grp, int tid) {
    __syncthreads();                 // all threads' state STGs issued
    if (tid == 0) {
        __threadfence();             // gpu-scope release
        atomicAdd(&g_prod[grp * 32], 1u);
    }
}

// ---------------- persistent recurrence kernel ----------------
__global__ void __launch_bounds__(NT, 1) rnn_kernel(
    const float* __restrict__ Wi,   // [NHID][NINP]
    const float* __restrict__ Wib,  // [NHID]
    const float* __restrict__ Wh,   // [NHID][NHID]
    const float* __restrict__ Ag,   // [NHID]
    const float* __restrict__ Om)   // [NHID]
{
    extern __shared__ float sm[];
    float* whs  = sm;                        // [k][16h], h contiguous
    float* xbuf = whs + WHS_FLOATS;          // [i][b]
    float* wis  = xbuf + XBUF_FLOATS;        // [i][h]
    float* red  = wis + WIS_FLOATS;          // 8 x 32 x 36

    const int tid  = threadIdx.x;
    const int wrp  = tid >> 5;
    const int lane = tid & 31;
    const int hg   = lane >> 3;              // h group: h = hg*4 .. hg*4+3
    const int bg   = lane & 7;               // b quad within each 32-half
    const int h0g  = blockIdx.x * HT;
    const int grp  = blockIdx.x >> 3;

    // epilogue ownership (bijective over 16h x 16 b-quads):
    const int eh  = ((tid >> 6) << 2) | ((tid >> 1) & 3);
    const int ebq = ((tid & 1) << 3) | ((tid >> 3) & 7);   // float4 index over b

    // One-time loads
    for (int idx = tid; idx < HT * NHID; idx += NT) {
        int h = idx >> 11;
        int k = idx & (NHID - 1);
        whs[k * HT + h] = Wh[(size_t)(h0g + h) * NHID + k];
    }
    for (int idx = tid; idx < HT * NINP; idx += NT) {
        int h = idx >> 6;
        int i = idx & 63;
        wis[i * HT + h] = Wi[(h0g + h) * NINP + i];
    }
    for (int idx = tid; idx < HT * BATCH; idx += NT) {
        g_sT[0][(h0g + (idx >> 6)) * BATCH + (idx & 63)] = 1.0f;
    }

    const float A0  = Ag[h0g + eh];
    const float o0  = Om[h0g + eh];
    const float bi0 = Wib[h0g + eh];

    float st[4] = {1.0f, 1.0f, 1.0f, 1.0f};

    signal_store(grp, tid);                  // initial state published

    // rotated k range per CTA (spreads L2 line pressure); two contiguous segments
    const int kbase = (wrp * KPW + ((blockIdx.x & 127) << 4)) & (NHID - 1);
    int len1 = NHID - kbase; if (len1 > KPW) len1 = KPW;
    const int len2 = KPW - len1;

    for (int t = 0; t < T_STEPS; ++t) {
        const int cur = t & 1, nxt = cur ^ 1;
        const float* S = g_sT[cur];
        const unsigned epoch = (unsigned)(GRPSZ * (t + 1));

        // stage x_t (small; lands before u-loop)
        {
            const float* xsrc = g_xT + (size_t)t * (NINP * BATCH);
            #pragma unroll
            for (int j = 0; j < 4; ++j) { int v = tid + j * NT; cpa16(xbuf + v * 4, xsrc + v * 4); }
            cpa_commit();
        }
        // parallel all-flags wait (threads 0..15 poll one counter each)
        if (tid < NCHUNK) {
            unsigned v;
            do {
                asm volatile("ld.acquire.gpu.u32 %0, [%1];"
                             : "=r"(v) : "l"(&g_prod[tid * 32]) : "memory");
            } while (v < epoch);
        }
        __syncthreads();

        unsigned long long acc[4][4];
        #pragma unroll
        for (int h = 0; h < 4; ++h)
            #pragma unroll
            for (int p = 0; p < 4; ++p) acc[h][p] = 0ull;

        // main MAC loop: state from L2 (LDG.cg), weights from smem
        #pragma unroll
        for (int seg = 0; seg < 2; ++seg) {
            const int ks  = seg ? 0    : kbase;
            const int len = seg ? len2 : len1;
            const float*  sp = S + (size_t)ks * BATCH + bg * 4;
            const float4* wp = (const float4*)whs + ks * 4 + hg;
            #pragma unroll 8
            for (int ki = 0; ki < len; ++ki) {
                unsigned long long s0, s1, s2, s3;
                ldcg2(sp + ki * BATCH,      s0, s1);   // b: bg*4..bg*4+3
                ldcg2(sp + ki * BATCH + 32, s2, s3);   // b: 32+bg*4..+3
                float4 wq = wp[ki * 4];                // 4 h weights (broadcast LDS.128)
                unsigned long long w0 = pk2(wq.x), w1 = pk2(wq.y),
                                   w2 = pk2(wq.z), w3 = pk2(wq.w);
                fma2(acc[0][0], s0, w0); fma2(acc[0][1], s1, w0);
                fma2(acc[0][2], s2, w0); fma2(acc[0][3], s3, w0);
                fma2(acc[1][0], s0, w1); fma2(acc[1][1], s1, w1);
                fma2(acc[1][2], s2, w1); fma2(acc[1][3], s3, w1);
                fma2(acc[2][0], s0, w2); fma2(acc[2][1], s1, w2);
                fma2(acc[2][2], s2, w2); fma2(acc[2][3], s3, w2);
                fma2(acc[3][0], s0, w3); fma2(acc[3][1], s1, w3);
                fma2(acc[3][2], s2, w3); fma2(acc[3][3], s3, w3);
            }
        }

        // cross-warp k-reduction through smem (padded stride 36 floats)
        {
            float* myred = red + wrp * (32 * 36) + lane * 36;
            #pragma unroll
            for (int h = 0; h < 4; ++h) {
                ((ulonglong2*)(myred + h * 8))[0] = make_ulonglong2(acc[h][0], acc[h][1]);
                ((ulonglong2*)(myred + h * 8))[1] = make_ulonglong2(acc[h][2], acc[h][3]);
            }
        }
        cpa_wait0();                         // x landed (this thread's part)
        __syncthreads();                     // red + xbuf visible to all

        float r0 = 0.f, r1 = 0.f, r2 = 0.f, r3 = 0.f;
        {
            // reader (tid) gathers h' = (tid>>1)&3, half q = tid&1 from source lane
            // row (tid>>3): matches (eh, ebq) ownership above.
            const float* base = red + (tid >> 3) * 36 + ((tid * 4) & 31);
            #pragma unroll
            for (int w2 = 0; w2 < 8; ++w2) {
                float4 v = *(const float4*)(base + w2 * (32 * 36));
                r0 += v.x; r1 += v.y; r2 += v.z; r3 += v.w;
            }
        }

        // u_t = Wi x_t + b for this thread's (eh, 4b) outputs
        float ua0 = bi0, ua1 = bi0, ua2 = bi0, ua3 = bi0;
        const float4* xv = (const float4*)xbuf;
        #pragma unroll 8
        for (int i2 = 0; i2 < NINP; ++i2) {
            float4 xs = xv[i2 * 16 + ebq];
            float wI = wis[i2 * HT + eh];
            ua0 += xs.x * wI; ua1 += xs.y * wI; ua2 += xs.z * wI; ua3 += xs.w * wI;
        }

        // epilogue
        float n0 = A0 * cosf(o0 * st[0] + ua0) + r0;
        float n1 = A0 * cosf(o0 * st[1] + ua1) + r1;
        float n2 = A0 * cosf(o0 * st[2] + ua2) + r2;
        float n3 = A0 * cosf(o0 * st[3] + ua3) + r3;
        ((float4*)(g_sT[nxt] + (size_t)(h0g + eh) * BATCH))[ebq] = make_float4(n0, n1, n2, n3);
        st[0] = n0; st[1] = n1; st[2] = n2; st[3] = n3;

        signal_store(grp, tid);
    }
}

// ---------------- readout, split: out[b][o] = sum_h sT[h][b]*Wr[o][h] + Wrb[o] ----------
__global__ void readout_part(const float* __restrict__ Wr)
{
    const int o  = blockIdx.x >> 3;
    const int sl = blockIdx.x & 7;
    const int b  = threadIdx.x;              // 64 threads
    const float* S  = g_sT[0];               // final state (t=511 wrote buf 0)
    const float* wr = Wr + (size_t)o * NHID;
    float acc = 0.f;
    const int h0 = sl * (NHID / 8);
    #pragma unroll 4
    for (int h = h0; h < h0 + NHID / 8; ++h)
        acc += S[h * BATCH + b] * wr[h];
    g_rpart[sl][o][b] = acc;
}

__global__ void readout_comb(const float* __restrict__ Wrb, float* __restrict__ out)
{
    const int o = blockIdx.x;
    const int b = threadIdx.x;               // 64 threads
    float acc = Wrb[o];
    #pragma unroll
    for (int sl = 0; sl < 8; ++sl) acc += g_rpart[sl][o][b];
    out[b * NOUT + o] = acc;
}

// ---------------- launch ----------------
extern "C" void kernel_launch(void* const* d_in, const int* in_sizes, int n_in,
                              void* d_out, int out_size) {
    const float* x   = (const float*)d_in[0];
    const float* Wi  = (const float*)d_in[1];
    const float* Wib = (const float*)d_in[2];
    const float* Wh  = (const float*)d_in[3];
    const float* A   = (const float*)d_in[4];
    const float* Om  = (const float*)d_in[5];
    const float* Wr  = (const float*)d_in[6];
    const float* Wrb = (const float*)d_in[7];
    float* out = (float*)d_out;

    cudaFuncSetAttribute(rnn_kernel, cudaFuncAttributeMaxDynamicSharedMemorySize, SMEM_BYTES);

    reset_kernel<<<1, 32>>>();               // launch 0
    transpose_x_kernel<<<T_STEPS, 256>>>(x); // launch 1
    dummy_kernel<<<1, 32>>>();               // launch 2
    rnn_kernel<<<NB, NT, SMEM_BYTES>>>(Wi, Wib, Wh, A, Om);   // launch 3 (ncu target)
    readout_part<<<NOUT * 8, BATCH>>>(Wr);   // launch 4
    readout_comb<<<NOUT, BATCH>>>(Wrb, out); // launch 5
}

// round 12
// speedup vs baseline: 3.1889x; 1.1115x over previous
#include <cuda_runtime.h>
#include <cstdint>
#include <math.h>

#define T_STEPS 512
#define BATCH   64
#define NHID    2048
#define NINP    64
#define NOUT    64

#define NB 128
#define NT 512                    // 16 warps = 4 per SMSP
#define HT 16
#define KPW (NHID / 16)           // 128 k-rows per warp
#define NCHUNK 16
#define GRPSZ  (NB / NCHUNK)

#define WHS_FLOATS (HT * NHID)            // 32768
#define XBUF_FLOATS (NINP * BATCH)        // 4096
#define WIS_FLOATS (NINP * HT)            // 1024
#define RED_FLOATS (16 * 32 * 36)         // 18432
#define SMEM_FLOATS (WHS_FLOATS + XBUF_FLOATS + WIS_FLOATS + RED_FLOATS)
#define SMEM_BYTES  (SMEM_FLOATS * 4)     // 225280

__device__ float    g_sT[2][NHID * BATCH];
__device__ float    g_xT[T_STEPS * NINP * BATCH];
__device__ unsigned g_prod[NCHUNK * 32];
__device__ float    g_rpart[8][NOUT][BATCH];

__global__ void reset_kernel() {
    if (threadIdx.x < NCHUNK) g_prod[threadIdx.x * 32] = 0u;
}
__global__ void dummy_kernel() {}   // keeps rnn_kernel at ncu's launch index 3

__global__ void transpose_x_kernel(const float* __restrict__ x) {
    __shared__ float xs[BATCH * (NINP + 1)];
    const int t = blockIdx.x;
    const float* xt = x + (size_t)t * (BATCH * NINP);
    for (int idx = threadIdx.x; idx < BATCH * NINP; idx += blockDim.x) {
        int b = idx >> 6, i = idx & 63;
        xs[b * (NINP + 1) + i] = xt[idx];
    }
    __syncthreads();
    float* dst = g_xT + (size_t)t * (NINP * BATCH);
    for (int idx = threadIdx.x; idx < NINP * BATCH; idx += blockDim.x) {
        int i = idx >> 6, b = idx & 63;
        dst[idx] = xs[b * (NINP + 1) + i];
    }
}

__device__ __forceinline__ void cpa16(float* s, const float* g) {
    unsigned sa = (unsigned)__cvta_generic_to_shared(s);
    asm volatile("cp.async.cg.shared.global [%0], [%1], 16;" :: "r"(sa), "l"(g) : "memory");
}
__device__ __forceinline__ void cpa_commit() { asm volatile("cp.async.commit_group;" ::: "memory"); }
__device__ __forceinline__ void cpa_wait0()  { asm volatile("cp.async.wait_group 0;" ::: "memory"); }

__device__ __forceinline__ unsigned long long pk2(float v) {
    unsigned long long r;
    asm("mov.b64 %0, {%1, %1};" : "=l"(r) : "f"(v));
    return r;
}
__device__ __forceinline__ void fma2(unsigned long long& d, unsigned long long a, unsigned long long b) {
    asm("fma.rn.f32x2 %0, %1, %2, %0;" : "+l"(d) : "l"(a), "l"(b));
}
__device__ __forceinline__ void ldcg2(const float* p, unsigned long long& a, unsigned long long& b) {
    asm volatile("ld.global.cg.v2.u64 {%0, %1}, [%2];" : "=l"(a), "=l"(b) : "l"(p));
}

__device__ __forceinline__ void signal_store(int grp, int tid) {
    __syncthreads();
    if (tid == 0) {
        __threadfence();
        atomicAdd(&g_prod[grp * 32], 1u);
    }
}

__global__ void __launch_bounds__(NT, 1) rnn_kernel(
    const float* __restrict__ Wi, const float* __restrict__ Wib,
    const float* __restrict__ Wh, const float* __restrict__ Ag,
    const float* __restrict__ Om)
{
    extern __shared__ float sm[];
    float* whs  = sm;                        // [k][16h]
    float* xbuf = whs + WHS_FLOATS;          // [i][b]
    float* wis  = xbuf + XBUF_FLOATS;        // [i][h]
    float* red  = wis + WIS_FLOATS;          // 16 x 32 x 36

    const int tid  = threadIdx.x;
    const int wrp  = tid >> 5;               // 0..15, owns 128 k-rows
    const int lane = tid & 31;
    const int hg   = lane >> 3;
    const int bg   = lane & 7;
    const int h0g  = blockIdx.x * HT;
    const int grp  = blockIdx.x >> 3;

    // epilogue ownership (tid<256): bijective over 16h x 16 b-quads
    const int eh  = ((tid >> 6) << 2) | ((tid >> 1) & 3);
    const int ebq = ((tid & 1) << 3) | ((tid >> 3) & 7);

    for (int idx = tid; idx < HT * NHID; idx += NT) {
        int h = idx >> 11, k = idx & (NHID - 1);
        whs[k * HT + h] = Wh[(size_t)(h0g + h) * NHID + k];
    }
    for (int idx = tid; idx < HT * NINP; idx += NT) {
        int h = idx >> 6, i = idx & 63;
        wis[i * HT + h] = Wi[(h0g + h) * NINP + i];
    }
    for (int idx = tid; idx < HT * BATCH; idx += NT)
        g_sT[0][(h0g + (idx >> 6)) * BATCH + (idx & 63)] = 1.0f;

    const float A0  = Ag[h0g + eh];
    const float o0  = Om[h0g + eh];
    const float bi0 = Wib[h0g + eh];

    float st[4] = {1.0f, 1.0f, 1.0f, 1.0f};

    signal_store(grp, tid);

    // rotated k range per CTA/warp (spreads L2 pressure); two contiguous segments
    const int kbase = (wrp * KPW + ((blockIdx.x & 127) << 4)) & (NHID - 1);
    int len1 = NHID - kbase; if (len1 > KPW) len1 = KPW;
    const int len2 = KPW - len1;

    for (int t = 0; t < T_STEPS; ++t) {
        const int cur = t & 1, nxt = cur ^ 1;
        const float* S = g_sT[cur];
        const unsigned epoch = (unsigned)(GRPSZ * (t + 1));

        {   // stage x_t (1024 vec4, 2 per thread)
            const float* xsrc = g_xT + (size_t)t * (NINP * BATCH);
            #pragma unroll
            for (int j = 0; j < 2; ++j) { int v = tid + j * NT; cpa16(xbuf + v * 4, xsrc + v * 4); }
            cpa_commit();
        }
        if (tid < NCHUNK) {                  // parallel all-flags wait
            unsigned v;
            do {
                asm volatile("ld.acquire.gpu.u32 %0, [%1];"
                             : "=r"(v) : "l"(&g_prod[tid * 32]) : "memory");
            } while (v < epoch);
        }
        __syncthreads();

        unsigned long long acc[4][4];
        #pragma unroll
        for (int h = 0; h < 4; ++h)
            #pragma unroll
            for (int p = 0; p < 4; ++p) acc[h][p] = 0ull;

        #pragma unroll
        for (int seg = 0; seg < 2; ++seg) {
            const int ks  = seg ? 0    : kbase;
            const int len = seg ? len2 : len1;
            const float*  sp = S + (size_t)ks * BATCH + bg * 4;
            const float4* wp = (const float4*)whs + ks * 4 + hg;
            #pragma unroll 8
            for (int ki = 0; ki < len; ++ki) {
                unsigned long long s0, s1, s2, s3;
                ldcg2(sp + ki * BATCH,      s0, s1);
                ldcg2(sp + ki * BATCH + 32, s2, s3);
                float4 wq = wp[ki * 4];
                unsigned long long w0 = pk2(wq.x), w1 = pk2(wq.y),
                                   w2 = pk2(wq.z), w3 = pk2(wq.w);
                fma2(acc[0][0], s0, w0); fma2(acc[0][1], s1, w0);
                fma2(acc[0][2], s2, w0); fma2(acc[0][3], s3, w0);
                fma2(acc[1][0], s0, w1); fma2(acc[1][1], s1, w1);
                fma2(acc[1][2], s2, w1); fma2(acc[1][3], s3, w1);
                fma2(acc[2][0], s0, w2); fma2(acc[2][1], s1, w2);
                fma2(acc[2][2], s2, w2); fma2(acc[2][3], s3, w2);
                fma2(acc[3][0], s0, w3); fma2(acc[3][1], s1, w3);
                fma2(acc[3][2], s2, w3); fma2(acc[3][3], s3, w3);
            }
        }

        {   // k-partials to smem (padded stride 36)
            float* myred = red + wrp * (32 * 36) + lane * 36;
            #pragma unroll
            for (int h = 0; h < 4; ++h) {
                ((ulonglong2*)(myred + h * 8))[0] = make_ulonglong2(acc[h][0], acc[h][1]);
                ((ulonglong2*)(myred + h * 8))[1] = make_ulonglong2(acc[h][2], acc[h][3]);
            }
        }
        cpa_wait0();
        __syncthreads();

        if (tid < 256) {
            float r0 = 0.f, r1 = 0.f, r2 = 0.f, r3 = 0.f;
            const float* base = red + (tid >> 3) * 36 + ((tid * 4) & 31);
            #pragma unroll
            for (int w2 = 0; w2 < 16; ++w2) {
                float4 v = *(const float4*)(base + w2 * (32 * 36));
                r0 += v.x; r1 += v.y; r2 += v.z; r3 += v.w;
            }

            float ua0 = bi0, ua1 = bi0, ua2 = bi0, ua3 = bi0;
            const float4* xv = (const float4*)xbuf;
            #pragma unroll 4
            for (int i2 = 0; i2 < NINP; ++i2) {
                float4 xs = xv[i2 * 16 + ebq];
                float wI = wis[i2 * HT + eh];
                ua0 += xs.x * wI; ua1 += xs.y * wI; ua2 += xs.z * wI; ua3 += xs.w * wI;
            }

            float n0 = A0 * cosf(o0 * st[0] + ua0) + r0;
            float n1 = A0 * cosf(o0 * st[1] + ua1) + r1;
            float n2 = A0 * cosf(o0 * st[2] + ua2) + r2;
            float n3 = A0 * cosf(o0 * st[3] + ua3) + r3;
            ((float4*)(g_sT[nxt] + (size_t)(h0g + eh) * BATCH))[ebq] = make_float4(n0, n1, n2, n3);
            st[0] = n0; st[1] = n1; st[2] = n2; st[3] = n3;
        }

        signal_store(grp, tid);
    }
}

__global__ void readout_part(const float* __restrict__ Wr)
{
    const int o  = blockIdx.x >> 3;
    const int sl = blockIdx.x & 7;
    const int b  = threadIdx.x;
    const float* S  = g_sT[0];
    const float* wr = Wr + (size_t)o * NHID;
    float acc = 0.f;
    const int h0 = sl * (NHID / 8);
    #pragma unroll 4
    for (int h = h0; h < h0 + NHID / 8; ++h)
        acc += S[h * BATCH + b] * wr[h];
    g_rpart[sl][o][b] = acc;
}

__global__ void readout_comb(const float* __restrict__ Wrb, float* __restrict__ out)
{
    const int o = blockIdx.x;
    const int b = threadIdx.x;
    float acc = Wrb[o];
    #pragma unroll
    for (int sl = 0; sl < 8; ++sl) acc += g_rpart[sl][o][b];
    out[b * NOUT + o] = acc;
}

extern "C" void kernel_launch(void* const* d_in, const int* in_sizes, int n_in,
                              void* d_out, int out_size) {
    const float* x   = (const float*)d_in[0];
    const float* Wi  = (const float*)d_in[1];
    const float* Wib = (const float*)d_in[2];
    const float* Wh  = (const float*)d_in[3];
    const float* A   = (const float*)d_in[4];
    const float* Om  = (const float*)d_in[5];
    const float* Wr  = (const float*)d_in[6];
    const float* Wrb = (const float*)d_in[7];
    float* out = (float*)d_out;

    cudaFuncSetAttribute(rnn_kernel, cudaFuncAttributeMaxDynamicSharedMemorySize, SMEM_BYTES);

    reset_kernel<<<1, 32>>>();               // launch 0
    transpose_x_kernel<<<T_STEPS, 256>>>(x); // launch 1
    dummy_kernel<<<1, 32>>>();               // launch 2
    rnn_kernel<<<NB, NT, SMEM_BYTES>>>(Wi, Wib, Wh, A, Om);   // launch 3 (ncu target)
    readout_part<<<NOUT * 8, BATCH>>>(Wr);   // launch 4
    readout_comb<<<NOUT, BATCH>>>(Wrb, out); // launch 5
}